// round 1
// baseline (speedup 1.0000x reference)
#include <cuda_runtime.h>
#include <math.h>

// Problem constants
#define NB 8
#define NT 1024
#define NC 8
#define NF 513
#define NA 320

// Scratch (device globals; no runtime allocation)
__device__ float  g_ms[NB*NF*NT];        // normalized speech mask (B,F,T)
__device__ float  g_mn[NB*NF*NT];        // normalized noise mask  (B,F,T)
__device__ float2 g_psd_s[NB*NF*64];     // (B,F,C,C)
__device__ float2 g_psd_n[NB*NF*64];
__device__ float  g_e[NB*NC];
__device__ float  g_u[NB*NC];
__device__ float2 g_bf[NB*NF*NC];        // beamformer vector (B,F,C)

// ---------------------------------------------------------------------------
// Kernel 1: masks -> channel mean, clip, normalize over time
// grid = B*F blocks, 256 threads, 4 t per thread
// ---------------------------------------------------------------------------
__global__ void mask_norm_kernel(const float* __restrict__ mask_s,
                                 const float* __restrict__ mask_n) {
    int bf  = blockIdx.x;                 // b*NF + f
    int tid = threadIdx.x;
    const float* ms = mask_s + (size_t)bf * NC * NT;
    const float* mn = mask_n + (size_t)bf * NC * NT;

    float vs[4], vn[4];
    float sums = 0.f, sumn = 0.f;
#pragma unroll
    for (int k = 0; k < 4; k++) {
        int t = tid + k * 256;
        float a = 0.f, b = 0.f;
#pragma unroll
        for (int c = 0; c < 8; c++) {
            a += fmaxf(ms[c * NT + t], 1e-6f);
            b += fmaxf(mn[c * NT + t], 1e-6f);
        }
        vs[k] = a * 0.125f;
        vn[k] = b * 0.125f;
        sums += vs[k];
        sumn += vn[k];
    }
    // block reduction of (sums, sumn)
    __shared__ float reds[8], redn[8];
    int lane = tid & 31, w = tid >> 5;
#pragma unroll
    for (int d = 16; d >= 1; d >>= 1) {
        sums += __shfl_xor_sync(0xffffffffu, sums, d);
        sumn += __shfl_xor_sync(0xffffffffu, sumn, d);
    }
    if (lane == 0) { reds[w] = sums; redn[w] = sumn; }
    __syncthreads();
    float ts = 0.f, tn = 0.f;
#pragma unroll
    for (int i = 0; i < 8; i++) { ts += reds[i]; tn += redn[i]; }
    float rs = 1.0f / (ts + 1e-15f);
    float rn = 1.0f / (tn + 1e-15f);

    float* oms = g_ms + (size_t)bf * NT;
    float* omn = g_mn + (size_t)bf * NT;
#pragma unroll
    for (int k = 0; k < 4; k++) {
        int t = tid + k * 256;
        oms[t] = vs[k] * rs;
        omn[t] = vn[k] * rn;
    }
}

// ---------------------------------------------------------------------------
// Kernel 2: PSD accumulation, both matrices in one pass over data.
// grid = (57, B), 288 threads (9 warps). Warp w owns f = fblk*9 + w.
// Smem tile stages data[b, t0:t0+64, c, f0:f0+9] (coalesced gmem reads).
// ---------------------------------------------------------------------------
__global__ __launch_bounds__(288, 1)
void psd_kernel(const float2* __restrict__ data) {
    __shared__ float2 tile[9][8][65];     // [f_local][c][t] (+1 pad)
    int fblk = blockIdx.x, b = blockIdx.y;
    int f0 = fblk * 9;
    int tid = threadIdx.x, w = tid >> 5, lane = tid & 31;
    int f = f0 + w;

    float4 acc[36];
#pragma unroll
    for (int p = 0; p < 36; p++) acc[p] = make_float4(0.f, 0.f, 0.f, 0.f);

    const float2* dbase = data + (size_t)b * NT * NC * NF;
    const float* msb = g_ms + ((size_t)b * NF + f) * NT;
    const float* mnb = g_mn + ((size_t)b * NF + f) * NT;

    // decomposition for cooperative load: 4608 float2 per chunk, 16 per thread
    int r     = tid % 72;     // (c, fl) index
    int c_ld  = r / 9;
    int fl_ld = r % 9;
    int tb_ld = tid / 72;     // base t within chunk (0..3)

    for (int t0 = 0; t0 < NT; t0 += 64) {
#pragma unroll
        for (int it = 0; it < 16; it++) {
            int tt = tb_ld + it * 4;
            tile[fl_ld][c_ld][tt] =
                dbase[((size_t)(t0 + tt) * NC + c_ld) * NF + f0 + fl_ld];
        }
        __syncthreads();
#pragma unroll
        for (int s = 0; s < 2; s++) {
            int tt = lane + s * 32;
            float msv = msb[t0 + tt];
            float mnv = mnb[t0 + tt];
            float2 x[8];
#pragma unroll
            for (int c = 0; c < 8; c++) x[c] = tile[w][c][tt];
            int p = 0;
#pragma unroll
            for (int i = 0; i < 8; i++) {
#pragma unroll
                for (int j = i; j < 8; j++) {
                    float pre = x[i].x * x[j].x + x[i].y * x[j].y;
                    float pim = x[i].y * x[j].x - x[i].x * x[j].y;
                    acc[p].x += msv * pre;
                    acc[p].y += msv * pim;
                    acc[p].z += mnv * pre;
                    acc[p].w += mnv * pim;
                    p++;
                }
            }
        }
        __syncthreads();
    }

    // butterfly reduce over the 32 lanes
#pragma unroll
    for (int p = 0; p < 36; p++) {
#pragma unroll
        for (int d = 16; d >= 1; d >>= 1) {
            acc[p].x += __shfl_xor_sync(0xffffffffu, acc[p].x, d);
            acc[p].y += __shfl_xor_sync(0xffffffffu, acc[p].y, d);
            acc[p].z += __shfl_xor_sync(0xffffffffu, acc[p].z, d);
            acc[p].w += __shfl_xor_sync(0xffffffffu, acc[p].w, d);
        }
    }
    if (lane == 0) {
        float2* ps = g_psd_s + ((size_t)b * NF + f) * 64;
        float2* pn = g_psd_n + ((size_t)b * NF + f) * 64;
        int p = 0;
#pragma unroll
        for (int i = 0; i < 8; i++) {
#pragma unroll
            for (int j = i; j < 8; j++) {
                ps[i * 8 + j] = make_float2(acc[p].x, acc[p].y);
                pn[i * 8 + j] = make_float2(acc[p].z, acc[p].w);
                if (i != j) {
                    ps[j * 8 + i] = make_float2(acc[p].x, -acc[p].y);
                    pn[j * 8 + i] = make_float2(acc[p].z, -acc[p].w);
                }
                p++;
            }
        }
    }
}

// ---------------------------------------------------------------------------
// Kernel 3: attention reference feature + MLP -> e (B,C)
// grid = B*C blocks, 256 threads
// ---------------------------------------------------------------------------
__global__ void attn_kernel(const float* __restrict__ W_psd,
                            const float* __restrict__ b_psd,
                            const float* __restrict__ w_gvec,
                            const float* __restrict__ b_gvec) {
    int b = blockIdx.x >> 3;
    int c = blockIdx.x & 7;
    __shared__ float feat[NF];
    for (int f = threadIdx.x; f < NF; f += 256) {
        const float2* row = g_psd_s + (((size_t)b * NF + f) * 8 + c) * 8;
        float sr = 0.f, si = 0.f;
#pragma unroll
        for (int e = 0; e < 8; e++) {
            if (e != c) { sr += row[e].x; si += row[e].y; }
        }
        feat[f] = sqrtf(sr * sr + si * si) * (1.0f / 7.0f);
    }
    __syncthreads();

    float part = 0.f;
    for (int a = threadIdx.x; a < NA; a += 256) {
        float h = b_psd[a];
#pragma unroll 8
        for (int f = 0; f < NF; f++) h += feat[f] * W_psd[f * NA + a];
        part += tanhf(h) * w_gvec[a];
    }
    __shared__ float red[8];
    int lane = threadIdx.x & 31, w = threadIdx.x >> 5;
#pragma unroll
    for (int d = 16; d >= 1; d >>= 1)
        part += __shfl_xor_sync(0xffffffffu, part, d);
    if (lane == 0) red[w] = part;
    __syncthreads();
    if (threadIdx.x == 0) {
        float tot = 0.f;
#pragma unroll
        for (int i = 0; i < 8; i++) tot += red[i];
        g_e[b * NC + c] = tot + b_gvec[0];
    }
}

// ---------------------------------------------------------------------------
// Kernel 4: softmax over channels (scaling = 2)
// ---------------------------------------------------------------------------
__global__ void softmax_kernel() {
    int b = threadIdx.x;
    if (b < NB) {
        float mx = -1e30f;
#pragma unroll
        for (int c = 0; c < NC; c++) mx = fmaxf(mx, g_e[b * NC + c]);
        float ex[NC];
        float s = 0.f;
#pragma unroll
        for (int c = 0; c < NC; c++) {
            ex[c] = expf(2.0f * (g_e[b * NC + c] - mx));
            s += ex[c];
        }
        float inv = 1.0f / s;
#pragma unroll
        for (int c = 0; c < NC; c++) g_u[b * NC + c] = ex[c] * inv;
    }
}

// ---------------------------------------------------------------------------
// Kernel 5: MVDR solve, half-warp (16 lanes) per (b,f).
// Gauss-Jordan on [psd_n + eps*I | psd_s]; columns 8..15 end as
// inv(psd_n) @ psd_s. Then trace-normalize and apply u.
// ---------------------------------------------------------------------------
__global__ void mvdr_kernel() {
    int gt = blockIdx.x * blockDim.x + threadIdx.x;
    int gw = gt >> 4;                 // problem id = b*NF + f
    int hl = threadIdx.x & 15;        // column within augmented matrix
    if (gw >= NB * NF) return;        // whole warps exit together (4104 even)
    int b = gw / NF;

    const float2* Pn = g_psd_n + (size_t)gw * 64;
    const float2* Ps = g_psd_s + (size_t)gw * 64;

    float2 m[8];
#pragma unroll
    for (int r0 = 0; r0 < 8; r0++)
        m[r0] = (hl < 8) ? Pn[r0 * 8 + hl] : Ps[r0 * 8 + (hl - 8)];
    if (hl < 8) {
#pragma unroll
        for (int r0 = 0; r0 < 8; r0++)
            if (r0 == hl) m[r0].x += 1e-15f;
    }

#pragma unroll
    for (int k = 0; k < 8; k++) {
        float pr = __shfl_sync(0xffffffffu, m[k].x, k, 16);
        float pi = __shfl_sync(0xffffffffu, m[k].y, k, 16);
        float den = pr * pr + pi * pi;
        float id  = 1.0f / den;
        float ir  =  pr * id;
        float ii  = -pi * id;
        float nr = m[k].x * ir - m[k].y * ii;
        float ni = m[k].x * ii + m[k].y * ir;
        m[k].x = nr; m[k].y = ni;
#pragma unroll
        for (int i = 0; i < 8; i++) {
            if (i == k) continue;
            float fr = __shfl_sync(0xffffffffu, m[i].x, k, 16);
            float fi = __shfl_sync(0xffffffffu, m[i].y, k, 16);
            m[i].x -= fr * m[k].x - fi * m[k].y;
            m[i].y -= fr * m[k].y + fi * m[k].x;
        }
    }

    // trace of num (held in lanes 8..15: column c = hl-8, diag entry row c)
    float tr_r = 0.f, tr_i = 0.f;
#pragma unroll
    for (int d = 0; d < 8; d++) {
        if (hl == 8 + d) { tr_r = m[d].x; tr_i = m[d].y; }
    }
#pragma unroll
    for (int d = 8; d >= 1; d >>= 1) {
        tr_r += __shfl_xor_sync(0xffffffffu, tr_r, d, 16);
        tr_i += __shfl_xor_sync(0xffffffffu, tr_i, d, 16);
    }
    tr_r += 1e-15f;
    float tden = tr_r * tr_r + tr_i * tr_i;
    float tid_ = 1.0f / tden;
    float itr_r =  tr_r * tid_;
    float itr_i = -tr_i * tid_;

    // bf[e] = (sum_c num[e][c] * u[c]) / trace
    float uc = (hl >= 8) ? g_u[b * NC + (hl - 8)] : 0.0f;
    float pr_[8], pi_[8];
#pragma unroll
    for (int e = 0; e < 8; e++) { pr_[e] = m[e].x * uc; pi_[e] = m[e].y * uc; }
#pragma unroll
    for (int e = 0; e < 8; e++) {
#pragma unroll
        for (int d = 8; d >= 1; d >>= 1) {
            pr_[e] += __shfl_xor_sync(0xffffffffu, pr_[e], d, 16);
            pi_[e] += __shfl_xor_sync(0xffffffffu, pi_[e], d, 16);
        }
    }
    if (hl == 0) {
        float2* out = g_bf + (size_t)gw * NC;
#pragma unroll
        for (int e = 0; e < 8; e++) {
            out[e] = make_float2(pr_[e] * itr_r - pi_[e] * itr_i,
                                 pr_[e] * itr_i + pi_[e] * itr_r);
        }
    }
}

// ---------------------------------------------------------------------------
// Kernel 6: apply beamformer. enh[b,t,f] = sum_c conj(bf[b,f,c]) * data[b,t,c,f]
// grid = (64, B), 256 threads, 16 t per block, thread f-strided.
// ---------------------------------------------------------------------------
__global__ __launch_bounds__(256)
void apply_kernel(const float2* __restrict__ data, float2* __restrict__ out) {
    int b = blockIdx.y;
    int t0 = blockIdx.x * 16;
    int tid = threadIdx.x;
    int fa = tid;          // < 513 always
    int fb = tid + 256;    // < 513 always (max 511)
    bool hasC = (tid == 0);
    int fc = 512;

    float2 cba[8], cbb[8], cbc[8];
    const float2* bfb = g_bf + (size_t)b * NF * NC;
#pragma unroll
    for (int c = 0; c < 8; c++) {
        float2 v = bfb[fa * NC + c]; cba[c] = make_float2(v.x, -v.y);
        float2 w = bfb[fb * NC + c]; cbb[c] = make_float2(w.x, -w.y);
    }
    if (hasC) {
#pragma unroll
        for (int c = 0; c < 8; c++) {
            float2 v = bfb[fc * NC + c]; cbc[c] = make_float2(v.x, -v.y);
        }
    }

    for (int tl = 0; tl < 16; tl++) {
        int t = t0 + tl;
        const float2* base = data + ((size_t)(b * NT + t) * NC) * NF;
        float2 a0 = make_float2(0.f, 0.f);
        float2 a1 = make_float2(0.f, 0.f);
        float2 a2 = make_float2(0.f, 0.f);
#pragma unroll
        for (int c = 0; c < 8; c++) {
            float2 d0 = base[c * NF + fa];
            a0.x += cba[c].x * d0.x - cba[c].y * d0.y;
            a0.y += cba[c].x * d0.y + cba[c].y * d0.x;
            float2 d1 = base[c * NF + fb];
            a1.x += cbb[c].x * d1.x - cbb[c].y * d1.y;
            a1.y += cbb[c].x * d1.y + cbb[c].y * d1.x;
        }
        if (hasC) {
#pragma unroll
            for (int c = 0; c < 8; c++) {
                float2 d2 = base[c * NF + fc];
                a2.x += cbc[c].x * d2.x - cbc[c].y * d2.y;
                a2.y += cbc[c].x * d2.y + cbc[c].y * d2.x;
            }
        }
        float2* ob = out + (size_t)(b * NT + t) * NF;
        ob[fa] = a0;
        ob[fb] = a1;
        if (hasC) ob[fc] = a2;
    }
}

// ---------------------------------------------------------------------------
extern "C" void kernel_launch(void* const* d_in, const int* in_sizes, int n_in,
                              void* d_out, int out_size) {
    const float* data_ri     = (const float*)d_in[0];
    const float* mask_speech = (const float*)d_in[1];
    const float* mask_noise  = (const float*)d_in[2];
    const float* W_psd       = (const float*)d_in[3];
    const float* b_psd       = (const float*)d_in[4];
    const float* w_gvec      = (const float*)d_in[5];
    const float* b_gvec      = (const float*)d_in[6];
    (void)in_sizes; (void)n_in; (void)out_size;

    const float2* data2 = (const float2*)data_ri;
    float2* out2 = (float2*)d_out;

    mask_norm_kernel<<<NB * NF, 256>>>(mask_speech, mask_noise);
    psd_kernel<<<dim3(57, NB), 288>>>(data2);
    attn_kernel<<<NB * NC, 256>>>(W_psd, b_psd, w_gvec, b_gvec);
    softmax_kernel<<<1, 32>>>();
    {
        int total = NB * NF * 16;                 // 16 threads per problem
        int threads = 256;
        int blocks = (total + threads - 1) / threads;
        mvdr_kernel<<<blocks, threads>>>();
    }
    apply_kernel<<<dim3(64, NB), 256>>>(data2, out2);
}